// round 15
// baseline (speedup 1.0000x reference)
#include <cuda_runtime.h>

// ---------------------------------------------------------------------------
// PureGNN rank collapse, u-scaled, CSR-pull pipeline (atomic-free passes):
//   build CSR(dst) once -> 3 gather passes compute z/u inline (double-buffered
//   u_A/u_B) -> pass3 pools -> tiny readout (chained weights + tanh head).
// Basis: [P^3 x, P^3 1, P^2 1, P 1, 1].
// Self-restoring invariants: g_cnt==0 restored by k_build, g_S==0 by k_readout.
// RULES: device globals only referenced in device code (ATS trap).
//        PDL pre-sync reads ONLY pure inputs or K-2-or-older data.
//        1 edge/thread for atomic kernels (R10/R12/R13 lesson).
// ---------------------------------------------------------------------------

#define NN 50000
#define NE 1600000
#define NG 32
#define ED 128
#define SCB 196          // ceil(NN/256) scan blocks

__device__ int    g_cnt [NN];       // invariant: 0 at kernel_launch entry
__device__ int    g_part[SCB];
__device__ int    g_off [NN + 1];
__device__ int    g_cur [NN];
__device__ int    g_col [NE];
__device__ float  g_dinv[NN];
__device__ float2 g_uA  [NN];
__device__ float2 g_uB  [NN];
__device__ float  g_k1y [NN];
__device__ float  g_k2y [NN];
__device__ float  g_S   [NG * 5];   // invariant: 0 at kernel_launch entry

// ---------------------------------------------------------------------------
// degree count into g_cnt (starts 0), 1 edge/thread
__global__ void k_count(const int* __restrict__ dst) {
    int e = blockIdx.x * blockDim.x + threadIdx.x;
    int d = 0;
    bool ok = (e < NE);
    if (ok) d = dst[e];                      // pure input: pre-sync
    cudaGridDependencySynchronize();         // prior replay's readout done
    if (ok) atomicAdd(&g_cnt[d], 1);
    cudaTriggerProgrammaticLaunchCompletion();
}

// per-block partial sums of g_cnt
__global__ void k_scan1() {
    __shared__ int sh[256];
    int i = blockIdx.x * 256 + threadIdx.x;
    cudaGridDependencySynchronize();         // cnt ready (count = K-1)
    sh[threadIdx.x] = (i < NN) ? g_cnt[i] : 0;
    __syncthreads();
    for (int o = 128; o > 0; o >>= 1) {
        if (threadIdx.x < o) sh[threadIdx.x] += sh[threadIdx.x + o];
        __syncthreads();
    }
    if (threadIdx.x == 0) g_part[blockIdx.x] = sh[0];
    cudaTriggerProgrammaticLaunchCompletion();
}

// build offsets/cursors + dinv + u0 + restore cnt=0.
// Pre-sync: cnt (count = K-2, safe) and x (pure) -> in-block scan overlapped.
// Post-sync: g_part (scan1 = K-1) -> block base.
__global__ void k_build(const float* __restrict__ x) {
    __shared__ int s1[256], s2[256], sp[256], sb[256];
    int t = threadIdx.x;
    int b = blockIdx.x;
    int i = b * 256 + t;

    int   c  = (i < NN) ? g_cnt[i] : 0;      // K-2: safe pre-sync
    float xi = (i < NN) ? x[i] : 0.0f;       // pure input

    // in-block inclusive scan of c (Hillis-Steele, ping-pong)
    s1[t] = c;
    __syncthreads();
    int* pin = s1; int* pout = s2;
    for (int o = 1; o < 256; o <<= 1) {
        pout[t] = pin[t] + ((t >= o) ? pin[t - o] : 0);
        __syncthreads();
        int* tmp = pin; pin = pout; pout = tmp;
    }
    int excl = pin[t] - c;

    cudaGridDependencySynchronize();         // g_part ready
    sp[t] = (t < SCB) ? g_part[t] : 0;
    sb[t] = (t < b && t < SCB) ? sp[t] : 0;
    __syncthreads();
    for (int o = 128; o > 0; o >>= 1) {
        if (t < o) sb[t] += sb[t + o];
        __syncthreads();
    }
    int base = sb[0];

    if (i < NN) {
        int off = base + excl;
        g_off[i] = off;
        g_cur[i] = off;
        float di = rsqrtf((float)c + 1.0f);  // +1 self-loop
        g_dinv[i] = di;
        g_uA[i] = make_float2(di * xi, di);
        g_cnt[i] = 0;                        // restore invariant
        if (i == NN - 1) g_off[NN] = off + c;
    }
    cudaTriggerProgrammaticLaunchCompletion();
}

// CSR fill: col[p] = src, 1 edge/thread
__global__ void k_fill(const int* __restrict__ src, const int* __restrict__ dst) {
    int e = blockIdx.x * blockDim.x + threadIdx.x;
    int s = 0, d = 0;
    bool ok = (e < NE);
    if (ok) { s = src[e]; d = dst[e]; }      // pure inputs: pre-sync
    cudaGridDependencySynchronize();         // cursors ready (build = K-1)
    if (ok) {
        int p = atomicAdd(&g_cur[d], 1);
        g_col[p] = s;
    }
    cudaTriggerProgrammaticLaunchCompletion();
}

// CSR pull pass K: warp-per-node; z = dinv*(row_sum + u_self); u_next = dinv*z.
// K=1: uA -> uB (stash z1.y); K=2: uB -> uA (stash z2.y); K=3: uA -> pool.
// Exactly 50000 fully-active warps (3125 blocks x 16 warps) -> collectives safe.
template <int K>
__global__ __launch_bounds__(512)
void k_pass(const int* __restrict__ batch) {
    __shared__ float sh[NG * 5];             // used by K==3 only
    int tid  = threadIdx.x;
    int lane = tid & 31;
    int w    = (blockIdx.x * 512 + tid) >> 5;   // node id, 0..NN-1

    // pre-sync: build outputs are K-2-or-older for every pass
    int   off0 = g_off[w];
    int   off1 = g_off[w + 1];
    float di   = g_dinv[w];
    float2 uself = make_float2(0.0f, 0.0f);
    if (K == 1) uself = g_uA[w];             // build = K-2: safe
    int   gb = 0; float k1 = 0.0f;
    if (K == 3) { gb = batch[w]; k1 = g_k1y[w]; }   // pure + pass1 = K-2
    if (K == 3) {
        for (int t = tid; t < NG * 5; t += 512) sh[t] = 0.0f;
        __syncthreads();
    }

    cudaGridDependencySynchronize();

    if (K == 2) uself = g_uB[w];             // pass1 = K-1
    if (K == 3) uself = g_uA[w];             // pass2 = K-1
    float k2 = 0.0f;
    if (K == 3) k2 = g_k2y[w];

    const float2* __restrict__ uin = (K == 2) ? g_uB : g_uA;
    float sx = 0.0f, sy = 0.0f;
    for (int p = off0 + lane; p < off1; p += 32) {
        int s = g_col[p];
        float2 v = __ldg(&uin[s]);
        sx += v.x;
        sy += v.y;
    }
    #pragma unroll
    for (int o = 16; o > 0; o >>= 1) {
        sx += __shfl_down_sync(0xffffffffu, sx, o);
        sy += __shfl_down_sync(0xffffffffu, sy, o);
    }
    if (lane == 0) {
        float zx = di * (sx + uself.x);
        float zy = di * (sy + uself.y);
        if (K == 1) { g_k1y[w] = zy; g_uB[w] = make_float2(di * zx, di * zy); }
        if (K == 2) { g_k2y[w] = zy; g_uA[w] = make_float2(di * zx, di * zy); }
        if (K == 3) {
            atomicAdd(&sh[gb * 5 + 0], zx);
            atomicAdd(&sh[gb * 5 + 1], zy);
            atomicAdd(&sh[gb * 5 + 2], k2);
            atomicAdd(&sh[gb * 5 + 3], k1);
            atomicAdd(&sh[gb * 5 + 4], 1.0f);
        }
    }
    if (K == 3) {
        __syncthreads();
        for (int t = tid; t < NG * 5; t += 512)
            if (sh[t] != 0.0f) atomicAdd(&g_S[t], sh[t]);
    }
    cudaTriggerProgrammaticLaunchCompletion();
}

// ---------------------------------------------------------------------------
// Readout (PDL): weight chain pre-sync (overlaps pass3); g_S read post-sync
// and zeroed to restore the replay invariant.
// ---------------------------------------------------------------------------
__global__ void k_readout(const float* __restrict__ lin_w, const float* __restrict__ lin_b,
                          const float* __restrict__ gcn_w, const float* __restrict__ gcn_b,
                          const float* __restrict__ r1_w,  const float* __restrict__ r1_b,
                          const float* __restrict__ r2_w,  const float* __restrict__ r2_b,
                          float* __restrict__ out) {
    __shared__ float vin[5][ED];
    __shared__ float vout[5][ED];
    __shared__ float pooled[NG][ED];
    __shared__ float hr[NG][ED];
    __shared__ float sS[NG * 5];

    int tid = threadIdx.x;
    int j   = tid & 127;
    int grp = tid >> 7;      // 0..3

    if (grp == 0) { vin[0][j] = lin_w[j]; vin[1][j] = lin_b[j]; }  // pure inputs
    __syncthreads();

    int nrows = 2;
    for (int l = 0; l < 3; l++) {
        const float* W = gcn_w + l * ED * ED;
        if (grp < nrows) {
            float a0 = 0.0f, a1 = 0.0f;
            #pragma unroll 4
            for (int i = 0; i < ED; i += 2) {
                a0 = fmaf(vin[grp][i],     W[i * ED + j],       a0);
                a1 = fmaf(vin[grp][i + 1], W[(i + 1) * ED + j], a1);
            }
            vout[grp][j] = a0 + a1;
        }
        if (grp == 0) vout[nrows][j] = gcn_b[l * ED + j];
        nrows++;
        __syncthreads();
        for (int r = grp; r < nrows; r += 4) vin[r][j] = vout[r][j];
        __syncthreads();
    }

    cudaGridDependencySynchronize();          // g_S ready
    for (int t = tid; t < NG * 5; t += 512) { sS[t] = g_S[t]; g_S[t] = 0.0f; }
    __syncthreads();

    for (int g = grp * 8; g < grp * 8 + 8; g++) {
        float p = 0.0f;
        #pragma unroll
        for (int r = 0; r < 5; r++) p = fmaf(sS[g * 5 + r], vin[r][j], p);
        pooled[g][j] = p;
    }
    __syncthreads();

    float bj = r1_b[j];
    for (int g = grp * 8; g < grp * 8 + 8; g++) {
        float a0 = bj, a1 = 0.0f, a2 = 0.0f, a3 = 0.0f;
        #pragma unroll 2
        for (int i = 0; i < ED; i += 4) {
            a0 = fmaf(pooled[g][i],     r1_w[i * ED + j],       a0);
            a1 = fmaf(pooled[g][i + 1], r1_w[(i + 1) * ED + j], a1);
            a2 = fmaf(pooled[g][i + 2], r1_w[(i + 2) * ED + j], a2);
            a3 = fmaf(pooled[g][i + 3], r1_w[(i + 3) * ED + j], a3);
        }
        hr[g][j] = tanhf((a0 + a1) + (a2 + a3));
    }
    __syncthreads();

    int warp = tid >> 5;
    int lane = tid & 31;
    for (int g = warp; g < NG; g += 16) {
        float s = hr[g][lane]      * r2_w[lane]
                + hr[g][lane + 32] * r2_w[lane + 32]
                + hr[g][lane + 64] * r2_w[lane + 64]
                + hr[g][lane + 96] * r2_w[lane + 96];
        #pragma unroll
        for (int o = 16; o > 0; o >>= 1) s += __shfl_down_sync(0xffffffffu, s, o);
        if (lane == 0) out[g] = s + r2_b[0];
    }
}

// ---------------------------------------------------------------------------
template <typename KernT, typename... Args>
static inline void launch_pdl(KernT kern, int grid, int block, Args... args) {
    cudaLaunchConfig_t cfg = {};
    cfg.gridDim = dim3(grid, 1, 1);
    cfg.blockDim = dim3(block, 1, 1);
    cfg.dynamicSmemBytes = 0;
    cfg.stream = 0;
    cudaLaunchAttribute attr[1];
    attr[0].id = cudaLaunchAttributeProgrammaticStreamSerialization;
    attr[0].val.programmaticStreamSerializationAllowed = 1;
    cfg.attrs = attr;
    cfg.numAttrs = 1;
    cudaLaunchKernelEx(&cfg, kern, args...);
}

extern "C" void kernel_launch(void* const* d_in, const int* in_sizes, int n_in,
                              void* d_out, int out_size) {
    const float* x     = (const float*)d_in[0];
    const int*   eidx  = (const int*)  d_in[1];
    const int*   batch = (const int*)  d_in[2];
    const float* lin_w = (const float*)d_in[3];
    const float* lin_b = (const float*)d_in[4];
    const float* gcn_w = (const float*)d_in[5];
    const float* gcn_b = (const float*)d_in[6];
    const float* r1_w  = (const float*)d_in[7];
    const float* r1_b  = (const float*)d_in[8];
    const float* r2_w  = (const float*)d_in[9];
    const float* r2_b  = (const float*)d_in[10];
    float* out = (float*)d_out;

    const int* src = eidx;          // edge_index[0]
    const int* dst = eidx + NE;     // edge_index[1]

    int eb = (NE + 255) / 256;      // 6250
    int pb = (NN * 32) / 512;       // 3125 (exact: 50000 warps)

    launch_pdl(k_count, eb, 256, dst);
    launch_pdl(k_scan1, SCB, 256);
    launch_pdl(k_build, SCB, 256, x);
    launch_pdl(k_fill,  eb, 256, src, dst);

    launch_pdl(k_pass<1>, pb, 512, batch);   // uA -> uB, z1.y
    launch_pdl(k_pass<2>, pb, 512, batch);   // uB -> uA, z2.y
    launch_pdl(k_pass<3>, pb, 512, batch);   // uA -> pool -> g_S

    launch_pdl(k_readout, 1, 512,
               lin_w, lin_b, gcn_w, gcn_b, r1_w, r1_b, r2_w, r2_b, out);
}

// round 16
// speedup vs baseline: 1.5586x; 1.5586x over previous
#include <cuda_runtime.h>

// ---------------------------------------------------------------------------
// PureGNN rank collapse, u-scaled form, multi-launch + PDL (R14 structure):
//   u_k = dinv .* z_k ; edge: acc[d] += u_k[s] ; node: z=dinv*(acc+u), u=dinv*z
// Basis after 3 layers: [P^3 x, P^3 1, P^2 1, P 1, 1]; pooled S -> tiny readout.
// Self-restoring invariants (no init kernel): g_deg==0 restored by k_prep,
// g_S==0 restored by k_readout; loader zero-init provides the first epoch.
// RULES: __device__ globals only referenced in device code (ATS trap).
//        PDL pre-sync code reads ONLY pure inputs or K-2-or-older data.
//        COO + float2 RED is sector-minimal; CSR pull LOSES (R15 lesson).
//        Atomic-bound kernels: 1 edge/thread, small blocks (R10/R12/R13).
// ---------------------------------------------------------------------------

#define NN 50000
#define NE 1600000
#define NG 32
#define ED 128

__device__ float  g_deg [NN];     // invariant: 0 at kernel_launch entry
__device__ float  g_dinv[NN];
__device__ float2 g_u   [NN];     // current u_k
__device__ float2 g_acc [NN];     // edge accumulator
__device__ float  g_k1y [NN];     // z1.y
__device__ float  g_k2y [NN];     // z2.y
__device__ float  g_S   [NG * 5]; // invariant: 0 at kernel_launch entry

// ---------------------------------------------------------------------------
// degree count: 2 edges/thread, indices pre-loaded; deg starts 0.
__global__ void k_count(const int* __restrict__ dst) {
    int e = (blockIdx.x * blockDim.x + threadIdx.x) * 2;
    int2 d2;
    bool full = (e + 1 < NE);
    if (full) d2 = *(const int2*)(dst + e);         // pure input: safe pre-sync
    cudaGridDependencySynchronize();                // prior replay's readout done
    if (full) {
        atomicAdd(&g_deg[d2.x], 1.0f);
        atomicAdd(&g_deg[d2.y], 1.0f);
    } else if (e < NE) {
        atomicAdd(&g_deg[dst[e]], 1.0f);
    }
    cudaTriggerProgrammaticLaunchCompletion();
}

// dinv = rsqrt(deg+1)  (+1 = self-loop); restore deg=0; u0; acc=0
__global__ void k_prep(const float* __restrict__ x) {
    int i = blockIdx.x * blockDim.x + threadIdx.x;
    float xi = 0.0f;
    if (i < NN) xi = x[i];
    cudaGridDependencySynchronize();                // wait for k_count
    if (i >= NN) return;
    float di = rsqrtf(g_deg[i] + 1.0f);
    g_deg[i] = 0.0f;                                // restore invariant
    g_dinv[i] = di;
    g_u[i]   = make_float2(di * xi, di);
    g_acc[i] = make_float2(0.0f, 0.0f);
}

// edge pass: acc[d] += u[s], ONE edge/thread, 128-thread blocks
__global__ void k_edge(const int* __restrict__ src, const int* __restrict__ dst) {
    int e = blockIdx.x * blockDim.x + threadIdx.x;
    int s = 0, d = 0;
    bool ok = (e < NE);
    if (ok) { s = src[e]; d = dst[e]; }             // pure input: safe pre-sync
    cudaGridDependencySynchronize();                // wait for u from prior kernel
    if (ok) atomicAdd(&g_acc[d], __ldg(&g_u[s]));
    cudaTriggerProgrammaticLaunchCompletion();
}

// node pass K (1 or 2): z = dinv*(acc+u); stash z.y; u = dinv*z; acc = 0
// dinv/u are K-2-or-older -> safe pre-sync; acc needs the sync.
template <int K>
__global__ void k_node() {
    int i = blockIdx.x * blockDim.x + threadIdx.x;
    float di = 0.0f; float2 u = make_float2(0.0f, 0.0f);
    if (i < NN) { di = g_dinv[i]; u = g_u[i]; }
    cudaGridDependencySynchronize();                // wait for acc from edge pass
    if (i >= NN) return;
    float2 a = g_acc[i];
    float zx = di * (a.x + u.x);
    float zy = di * (a.y + u.y);
    if (K == 1) g_k1y[i] = zy;
    else        g_k2y[i] = zy;
    g_u[i]   = make_float2(di * zx, di * zy);
    g_acc[i] = make_float2(0.0f, 0.0f);
}

// node3 + per-graph pooling (batch sorted -> warp-uniform fast path).
__global__ void k_node3_pool(const int* __restrict__ batch) {
    __shared__ float sh[NG * 5];
    int i = blockIdx.x * blockDim.x + threadIdx.x;
    int lane = threadIdx.x & 31;
    bool act = (i < NN);
    int g = 0;
    if (act) g = batch[i];                          // pure input: safe pre-sync
    for (int t = threadIdx.x; t < NG * 5; t += blockDim.x) sh[t] = 0.0f;
    __syncthreads();

    cudaGridDependencySynchronize();                // wait for acc3

    float z3x = 0.0f, z3y = 0.0f, k2 = 0.0f, k1 = 0.0f;
    if (act) {
        float di = g_dinv[i];
        float2 a = g_acc[i];
        float2 u = g_u[i];
        z3x = di * (a.x + u.x);
        z3y = di * (a.y + u.y);
        k2  = g_k2y[i];
        k1  = g_k1y[i];
    }
    unsigned m = __ballot_sync(0xffffffffu, act);
    int g0 = __shfl_sync(0xffffffffu, g, 0);
    bool uni = (m == 0xffffffffu) && __all_sync(0xffffffffu, g == g0);
    if (uni) {
        #pragma unroll
        for (int o = 16; o > 0; o >>= 1) {
            z3x += __shfl_down_sync(0xffffffffu, z3x, o);
            z3y += __shfl_down_sync(0xffffffffu, z3y, o);
            k2  += __shfl_down_sync(0xffffffffu, k2,  o);
            k1  += __shfl_down_sync(0xffffffffu, k1,  o);
        }
        if (lane == 0) {
            atomicAdd(&sh[g0 * 5 + 0], z3x);
            atomicAdd(&sh[g0 * 5 + 1], z3y);
            atomicAdd(&sh[g0 * 5 + 2], k2);
            atomicAdd(&sh[g0 * 5 + 3], k1);
            atomicAdd(&sh[g0 * 5 + 4], 32.0f);
        }
    } else if (act) {
        atomicAdd(&sh[g * 5 + 0], z3x);
        atomicAdd(&sh[g * 5 + 1], z3y);
        atomicAdd(&sh[g * 5 + 2], k2);
        atomicAdd(&sh[g * 5 + 3], k1);
        atomicAdd(&sh[g * 5 + 4], 1.0f);
    }
    __syncthreads();
    for (int t = threadIdx.x; t < NG * 5; t += blockDim.x)
        if (sh[t] != 0.0f) atomicAdd(&g_S[t], sh[t]);
    cudaTriggerProgrammaticLaunchCompletion();
}

// ---------------------------------------------------------------------------
// Readout (PDL): weight chain pre-sync (overlaps the pool); g_S read post-sync
// and zeroed to restore the replay invariant.
// ---------------------------------------------------------------------------
__global__ void k_readout(const float* __restrict__ lin_w, const float* __restrict__ lin_b,
                          const float* __restrict__ gcn_w, const float* __restrict__ gcn_b,
                          const float* __restrict__ r1_w,  const float* __restrict__ r1_b,
                          const float* __restrict__ r2_w,  const float* __restrict__ r2_b,
                          float* __restrict__ out) {
    __shared__ float vin[5][ED];
    __shared__ float vout[5][ED];
    __shared__ float pooled[NG][ED];
    __shared__ float hr[NG][ED];
    __shared__ float sS[NG * 5];

    int tid = threadIdx.x;
    int j   = tid & 127;
    int grp = tid >> 7;      // 0..3

    if (grp == 0) { vin[0][j] = lin_w[j]; vin[1][j] = lin_b[j]; }  // pure inputs
    __syncthreads();

    int nrows = 2;
    for (int l = 0; l < 3; l++) {
        const float* W = gcn_w + l * ED * ED;
        if (grp < nrows) {
            float a0 = 0.0f, a1 = 0.0f;
            #pragma unroll 4
            for (int i = 0; i < ED; i += 2) {
                a0 = fmaf(vin[grp][i],     W[i * ED + j],       a0);
                a1 = fmaf(vin[grp][i + 1], W[(i + 1) * ED + j], a1);
            }
            vout[grp][j] = a0 + a1;
        }
        if (grp == 0) vout[nrows][j] = gcn_b[l * ED + j];
        nrows++;
        __syncthreads();
        for (int r = grp; r < nrows; r += 4) vin[r][j] = vout[r][j];
        __syncthreads();
    }

    cudaGridDependencySynchronize();          // g_S ready
    for (int t = tid; t < NG * 5; t += 512) { sS[t] = g_S[t]; g_S[t] = 0.0f; }
    __syncthreads();

    for (int g = grp * 8; g < grp * 8 + 8; g++) {
        float p = 0.0f;
        #pragma unroll
        for (int r = 0; r < 5; r++) p = fmaf(sS[g * 5 + r], vin[r][j], p);
        pooled[g][j] = p;
    }
    __syncthreads();

    float bj = r1_b[j];
    for (int g = grp * 8; g < grp * 8 + 8; g++) {
        float a0 = bj, a1 = 0.0f, a2 = 0.0f, a3 = 0.0f;
        #pragma unroll 2
        for (int i = 0; i < ED; i += 4) {
            a0 = fmaf(pooled[g][i],     r1_w[i * ED + j],       a0);
            a1 = fmaf(pooled[g][i + 1], r1_w[(i + 1) * ED + j], a1);
            a2 = fmaf(pooled[g][i + 2], r1_w[(i + 2) * ED + j], a2);
            a3 = fmaf(pooled[g][i + 3], r1_w[(i + 3) * ED + j], a3);
        }
        hr[g][j] = tanhf((a0 + a1) + (a2 + a3));
    }
    __syncthreads();

    int warp = tid >> 5;
    int lane = tid & 31;
    for (int g = warp; g < NG; g += 16) {
        float s = hr[g][lane]      * r2_w[lane]
                + hr[g][lane + 32] * r2_w[lane + 32]
                + hr[g][lane + 64] * r2_w[lane + 64]
                + hr[g][lane + 96] * r2_w[lane + 96];
        #pragma unroll
        for (int o = 16; o > 0; o >>= 1) s += __shfl_down_sync(0xffffffffu, s, o);
        if (lane == 0) out[g] = s + r2_b[0];
    }
}

// ---------------------------------------------------------------------------
template <typename KernT, typename... Args>
static inline void launch_pdl(KernT kern, int grid, int block, Args... args) {
    cudaLaunchConfig_t cfg = {};
    cfg.gridDim = dim3(grid, 1, 1);
    cfg.blockDim = dim3(block, 1, 1);
    cfg.dynamicSmemBytes = 0;
    cfg.stream = 0;
    cudaLaunchAttribute attr[1];
    attr[0].id = cudaLaunchAttributeProgrammaticStreamSerialization;
    attr[0].val.programmaticStreamSerializationAllowed = 1;
    cfg.attrs = attr;
    cfg.numAttrs = 1;
    cudaLaunchKernelEx(&cfg, kern, args...);
}

extern "C" void kernel_launch(void* const* d_in, const int* in_sizes, int n_in,
                              void* d_out, int out_size) {
    const float* x     = (const float*)d_in[0];
    const int*   eidx  = (const int*)  d_in[1];
    const int*   batch = (const int*)  d_in[2];
    const float* lin_w = (const float*)d_in[3];
    const float* lin_b = (const float*)d_in[4];
    const float* gcn_w = (const float*)d_in[5];
    const float* gcn_b = (const float*)d_in[6];
    const float* r1_w  = (const float*)d_in[7];
    const float* r1_b  = (const float*)d_in[8];
    const float* r2_w  = (const float*)d_in[9];
    const float* r2_b  = (const float*)d_in[10];
    float* out = (float*)d_out;

    const int* src = eidx;          // edge_index[0]
    const int* dst = eidx + NE;     // edge_index[1]

    int nb = (NN + 255) / 256;                 // 196
    int cb = (NE + 2 * 128 - 1) / (2 * 128);   // 6250 (128-thread blocks)
    int eb = (NE + 127) / 128;                 // 12500 (128-thread blocks)

    launch_pdl(k_count, cb, 128, dst);
    launch_pdl(k_prep,  nb, 256, x);

    launch_pdl(k_edge,  eb, 128, src, dst);    // acc1 = A u0
    launch_pdl(k_node<1>, nb, 256);            // z1, u1
    launch_pdl(k_edge,  eb, 128, src, dst);    // acc2 = A u1
    launch_pdl(k_node<2>, nb, 256);            // z2, u2
    launch_pdl(k_edge,  eb, 128, src, dst);    // acc3 = A u2
    launch_pdl(k_node3_pool, nb, 256, batch);  // z3 + pool -> g_S

    launch_pdl(k_readout, 1, 512,
               lin_w, lin_b, gcn_w, gcn_b, r1_w, r1_b, r2_w, r2_b, out);
}